// round 14
// baseline (speedup 1.0000x reference)
#include <cuda_runtime.h>
#include <cstdint>

// NormmaxBisect, alpha=1.5, d=2048: p = clamp(x - tau, 0)^2 / sum(...),
// tau solves sum(clamp(x - tau, 0)^3) = 1.
//
// Two-kernel split to keep each HBM stream pure-direction:
//   K1: zero-fill the whole output (pure write stream). Correct because
//       p = 0 exactly for every inactive element (x <= rowmax - 1).
//   K2: one warp per row, pure read stream: load row (two halves, streaming),
//       compact active (value,index) pairs into a per-warp smem list, solve
//       tau with 2 ballot-search rounds + 3 redundant-lane Newton steps, then
//       scatter only the few nonzero p values. Rare list-overflow rows take a
//       full-row gmem solve and rewrite their whole row.

#define D 2048
#define WARPS 8
#define THREADS 256
#define LISTCAP 224
#define NROUNDS 2
#define NN 3
#define NB_FB 22
#define DM0 0.9779029130879204f   // 1 - (1/2048)^0.5

static __device__ __forceinline__ float warp_max(float v) {
    #pragma unroll
    for (int o = 16; o; o >>= 1) v = fmaxf(v, __shfl_xor_sync(0xffffffffu, v, o));
    return v;
}
static __device__ __forceinline__ float warp_sum(float v) {
    #pragma unroll
    for (int o = 16; o; o >>= 1) v += __shfl_xor_sync(0xffffffffu, v, o);
    return v;
}

// ================= K1: pure-write zero fill =================
__global__ __launch_bounds__(256)
void zerofill_kernel(float4* __restrict__ out, long long n4) {
    const long long stride = (long long)gridDim.x * 256;
    const float4 z = make_float4(0.0f, 0.0f, 0.0f, 0.0f);
    for (long long i = (long long)blockIdx.x * 256 + threadIdx.x; i < n4; i += stride)
        __stcs(out + i, z);
}

// ---- fallback full-row sums from gmem (rare) ----
static __device__ __forceinline__ float s3_g(const float4* __restrict__ src, int lane, float tau) {
    float s3 = 0.0f;
    #pragma unroll 4
    for (int j = 0; j < 16; ++j) {
        float4 t = src[j * 32 + lane];
        float cx = fmaxf(t.x - tau, 0.0f), cy = fmaxf(t.y - tau, 0.0f);
        float cz = fmaxf(t.z - tau, 0.0f), cw = fmaxf(t.w - tau, 0.0f);
        s3 = fmaf(cx * cx, cx, s3); s3 = fmaf(cy * cy, cy, s3);
        s3 = fmaf(cz * cz, cz, s3); s3 = fmaf(cw * cw, cw, s3);
    }
    return warp_sum(s3);
}
static __device__ __forceinline__ void s23_g(const float4* __restrict__ src, int lane, float tau,
                                             float& s2o, float& s3o) {
    float s2 = 0.0f, s3 = 0.0f;
    #pragma unroll 4
    for (int j = 0; j < 16; ++j) {
        float4 t = src[j * 32 + lane];
        float cx = fmaxf(t.x - tau, 0.0f), cy = fmaxf(t.y - tau, 0.0f);
        float cz = fmaxf(t.z - tau, 0.0f), cw = fmaxf(t.w - tau, 0.0f);
        float c2x = cx * cx, c2y = cy * cy, c2z = cz * cz, c2w = cw * cw;
        s2 += c2x + c2y + c2z + c2w;
        s3 = fmaf(c2x, cx, s3); s3 = fmaf(c2y, cy, s3);
        s3 = fmaf(c2z, cz, s3); s3 = fmaf(c2w, cw, s3);
    }
    s2o = warp_sum(s2);
    s3o = warp_sum(s3);
}

// ================= K2: pure-read solve + sparse scatter =================
__global__ __launch_bounds__(THREADS, 5)
void normmax_solve_kernel(const float* __restrict__ X, float* __restrict__ O, int nrows) {
    __shared__ float lv[WARPS][LISTCAP];
    __shared__ int   li[WARPS][LISTCAP];

    const int wid  = threadIdx.x >> 5;
    const int lane = threadIdx.x & 31;
    const int w    = blockIdx.x * WARPS + wid;
    if (w >= nrows) return;
    float* Lv = lv[wid];
    int*   Li = li[wid];

    const float4* __restrict__ src = reinterpret_cast<const float4*>(X + (size_t)w * D);

    float4 f[8];

    // ================= half 0: elements [0, 1024) =================
    #pragma unroll
    for (int j = 0; j < 8; ++j) f[j] = __ldcs(src + j * 32 + lane);
    float lm = -3.4e38f;
    #pragma unroll
    for (int j = 0; j < 8; ++j)
        lm = fmaxf(lm, fmaxf(fmaxf(f[j].x, f[j].y), fmaxf(f[j].z, f[j].w)));
    const float wm1  = warp_max(lm);
    const float thr1 = wm1 - 1.0f;     // wm1 <= rowmax -> superset threshold

    int cnt = 0;
    #pragma unroll
    for (int j = 0; j < 8; ++j)
        cnt += (f[j].x > thr1) + (f[j].y > thr1) + (f[j].z > thr1) + (f[j].w > thr1);
    int pre = cnt;
    #pragma unroll
    for (int o = 1; o < 32; o <<= 1) {
        int t = __shfl_up_sync(0xffffffffu, pre, o);
        if (lane >= o) pre += t;
    }
    int total = __shfl_sync(0xffffffffu, pre, 31);
    bool ovf = total > LISTCAP;
    if (!ovf) {
        int k = pre - cnt;
        #pragma unroll
        for (int j = 0; j < 8; ++j) {
            const int e = 4 * (j * 32 + lane);
            if (f[j].x > thr1) { Lv[k] = f[j].x; Li[k] = e;     ++k; }
            if (f[j].y > thr1) { Lv[k] = f[j].y; Li[k] = e + 1; ++k; }
            if (f[j].z > thr1) { Lv[k] = f[j].z; Li[k] = e + 2; ++k; }
            if (f[j].w > thr1) { Lv[k] = f[j].w; Li[k] = e + 3; ++k; }
        }
    }

    // ================= half 1: elements [1024, 2048) =================
    #pragma unroll
    for (int j = 0; j < 8; ++j) f[j] = __ldcs(src + (j + 8) * 32 + lane);
    float lm2 = -3.4e38f;
    #pragma unroll
    for (int j = 0; j < 8; ++j)
        lm2 = fmaxf(lm2, fmaxf(fmaxf(f[j].x, f[j].y), fmaxf(f[j].z, f[j].w)));
    const float wm2 = warp_max(lm2);
    const float mx  = fmaxf(wm1, wm2);
    const float thr = mx - 1.0f;       // exact active threshold (= tau_lo)

    int cnt2 = 0;
    #pragma unroll
    for (int j = 0; j < 8; ++j)
        cnt2 += (f[j].x > thr) + (f[j].y > thr) + (f[j].z > thr) + (f[j].w > thr);
    int pre2 = cnt2;
    #pragma unroll
    for (int o = 1; o < 32; o <<= 1) {
        int t = __shfl_up_sync(0xffffffffu, pre2, o);
        if (lane >= o) pre2 += t;
    }
    const int tot2 = __shfl_sync(0xffffffffu, pre2, 31);
    if (total + tot2 > LISTCAP) ovf = true;
    if (!ovf) {
        int k = total + (pre2 - cnt2);
        #pragma unroll
        for (int j = 0; j < 8; ++j) {
            const int e = 4 * ((j + 8) * 32 + lane);
            if (f[j].x > thr) { Lv[k] = f[j].x; Li[k] = e;     ++k; }
            if (f[j].y > thr) { Lv[k] = f[j].y; Li[k] = e + 1; ++k; }
            if (f[j].z > thr) { Lv[k] = f[j].z; Li[k] = e + 2; ++k; }
            if (f[j].w > thr) { Lv[k] = f[j].w; Li[k] = e + 3; ++k; }
        }
    }
    total += tot2;
    __syncwarp();   // publish list

    if (!ovf) {
        // ---- 2 ballot-search rounds: 33-way bracket split per round ----
        float lo = thr;              // f(lo) >= 0 guaranteed (max element gives c=1)
        float wd = DM0;
        #pragma unroll
        for (int rnd = 0; rnd < NROUNDS; ++rnd) {
            const float step = wd * (1.0f / 33.0f);
            const float tm = lo + step * (float)(lane + 1);
            float s3 = 0.0f;
            for (int i = 0; i < total; ++i) {            // LDS broadcast reads
                float c = fmaxf(Lv[i] - tm, 0.0f);
                s3 = fmaf(c * c, c, s3);
            }
            const unsigned b = __ballot_sync(0xffffffffu, s3 >= 1.0f);
            const int m = 32 - __clz(b);   // satisfying lanes contiguous from 0
            lo += step * (float)m;         // f(lo) still >= 0
            wd = step;
        }

        // ---- 3 Newton steps, every lane redundant (warp-uniform tau) ----
        float tau = lo;
        #pragma unroll
        for (int it = 0; it < NN; ++it) {
            float s2 = 0.0f, s3 = 0.0f;
            for (int i = 0; i < total; ++i) {
                float c = fmaxf(Lv[i] - tau, 0.0f);
                float c2 = c * c;
                s2 += c2;
                s3 = fmaf(c2, c, s3);
            }
            tau += __fdividef(s3 - 1.0f, 3.0f * s2);   // convex, from f>=0 side
        }
        // ---- normalization ----
        float s2 = 0.0f;
        for (int i = 0; i < total; ++i) {
            float c = fmaxf(Lv[i] - tau, 0.0f);
            s2 = fmaf(c, c, s2);
        }
        const float inv = __fdividef(1.0f, s2);

        // ---- sparse scatter (zeros already written by K1) ----
        float* __restrict__ orow = O + (size_t)w * D;
        for (int i = lane; i < total; i += 32) {
            const float c = fmaxf(Lv[i] - tau, 0.0f);
            if (c > 0.0f) orow[Li[i]] = c * c * inv;
        }
    } else {
        // ---- rare fallback: full-row solve + full-row write ----
        float tau_lo = thr, dm = DM0;
        for (int it = 0; it < NB_FB; ++it) {
            dm *= 0.5f;
            const float tm = tau_lo + dm;
            if (s3_g(src, lane, tm) >= 1.0f) tau_lo = tm;
        }
        float tau = tau_lo;
        for (int it = 0; it < NN; ++it) {
            float rs2, rs3;
            s23_g(src, lane, tau, rs2, rs3);
            tau += __fdividef(rs3 - 1.0f, 3.0f * rs2);
        }
        float s2, dummy;
        s23_g(src, lane, tau, s2, dummy);
        const float inv = __fdividef(1.0f, s2);

        float4* __restrict__ dst = reinterpret_cast<float4*>(O + (size_t)w * D);
        #pragma unroll 4
        for (int j = 0; j < 16; ++j) {
            float4 t = src[j * 32 + lane];
            float cx = fmaxf(t.x - tau, 0.0f), cy = fmaxf(t.y - tau, 0.0f);
            float cz = fmaxf(t.z - tau, 0.0f), cw = fmaxf(t.w - tau, 0.0f);
            float4 p;
            p.x = cx * cx * inv;
            p.y = cy * cy * inv;
            p.z = cz * cz * inv;
            p.w = cw * cw * inv;
            dst[j * 32 + lane] = p;
        }
    }
}

extern "C" void kernel_launch(void* const* d_in, const int* in_sizes, int n_in,
                              void* d_out, int out_size) {
    const float* X = (const float*)d_in[0];
    float* O = (float*)d_out;
    const int nrows = in_sizes[0] / D;                 // 65536
    const long long n4 = (long long)out_size / 4;      // float4 count

    zerofill_kernel<<<4096, 256>>>((float4*)d_out, n4);
    const int grid = (nrows + WARPS - 1) / WARPS;
    normmax_solve_kernel<<<grid, THREADS>>>(X, O, nrows);
}

// round 15
// speedup vs baseline: 1.3722x; 1.3722x over previous
#include <cuda_runtime.h>
#include <cstdint>

// NormmaxBisect, alpha=1.5, d=2048: p = clamp(x - tau, 0)^2 / sum(...),
// tau solves sum(clamp(x - tau, 0)^3) = 1.
//
// Fused single kernel, one warp per row, instruction-trimmed solver:
//  - row read in two register halves (regs ~48 -> occ ~50%)
//  - actives (x > rowmax-1; half 0 uses the superset wm1-1) compacted with
//    indices into a per-warp smem list (deterministic prefix-scan order)
//  - solver: 2 lane-anchored ballot rounds (32-way bracket split each,
//    lane 0 sits on the proven f>=0 endpoint) -> bracket 9.55e-4; round 2
//    also accumulates s2 so Newton step 1 comes free via shfl from the
//    bracketing lane; +1 more Newton pass -> fp32-exact tau
//  - output: streaming zero-fill (p = 0 exactly for inactive elements)
//    + sparse scatter of the few nonzero p
//  - rare list-overflow rows: full-row gmem solve + full-row write

#define D 2048
#define WARPS 8
#define THREADS 256
#define LISTCAP 224
#define NB_FB 22
#define NN_FB 3
#define DM0 0.9779029130879204f   // 1 - (1/2048)^0.5

static __device__ __forceinline__ float warp_max(float v) {
    #pragma unroll
    for (int o = 16; o; o >>= 1) v = fmaxf(v, __shfl_xor_sync(0xffffffffu, v, o));
    return v;
}
static __device__ __forceinline__ float warp_sum(float v) {
    #pragma unroll
    for (int o = 16; o; o >>= 1) v += __shfl_xor_sync(0xffffffffu, v, o);
    return v;
}

// ---- fallback full-row sums from gmem (rare) ----
static __device__ __forceinline__ float s3_g(const float4* __restrict__ src, int lane, float tau) {
    float s3 = 0.0f;
    #pragma unroll 4
    for (int j = 0; j < 16; ++j) {
        float4 t = src[j * 32 + lane];
        float cx = fmaxf(t.x - tau, 0.0f), cy = fmaxf(t.y - tau, 0.0f);
        float cz = fmaxf(t.z - tau, 0.0f), cw = fmaxf(t.w - tau, 0.0f);
        s3 = fmaf(cx * cx, cx, s3); s3 = fmaf(cy * cy, cy, s3);
        s3 = fmaf(cz * cz, cz, s3); s3 = fmaf(cw * cw, cw, s3);
    }
    return warp_sum(s3);
}
static __device__ __forceinline__ void s23_g(const float4* __restrict__ src, int lane, float tau,
                                             float& s2o, float& s3o) {
    float s2 = 0.0f, s3 = 0.0f;
    #pragma unroll 4
    for (int j = 0; j < 16; ++j) {
        float4 t = src[j * 32 + lane];
        float cx = fmaxf(t.x - tau, 0.0f), cy = fmaxf(t.y - tau, 0.0f);
        float cz = fmaxf(t.z - tau, 0.0f), cw = fmaxf(t.w - tau, 0.0f);
        float c2x = cx * cx, c2y = cy * cy, c2z = cz * cz, c2w = cw * cw;
        s2 += c2x + c2y + c2z + c2w;
        s3 = fmaf(c2x, cx, s3); s3 = fmaf(c2y, cy, s3);
        s3 = fmaf(c2z, cz, s3); s3 = fmaf(c2w, cw, s3);
    }
    s2o = warp_sum(s2);
    s3o = warp_sum(s3);
}

__global__ __launch_bounds__(THREADS, 5)
void normmax_trim_kernel(const float* __restrict__ X, float* __restrict__ O, int nrows) {
    __shared__ float lv[WARPS][LISTCAP];
    __shared__ int   li[WARPS][LISTCAP];

    const int wid  = threadIdx.x >> 5;
    const int lane = threadIdx.x & 31;
    const int w    = blockIdx.x * WARPS + wid;
    if (w >= nrows) return;
    float* Lv = lv[wid];
    int*   Li = li[wid];

    const float4* __restrict__ src = reinterpret_cast<const float4*>(X + (size_t)w * D);
    float4* __restrict__ dst       = reinterpret_cast<float4*>(O + (size_t)w * D);

    float4 f[8];

    // ================= half 0: elements [0, 1024) =================
    #pragma unroll
    for (int j = 0; j < 8; ++j) f[j] = src[j * 32 + lane];
    float lm = -3.4e38f;
    #pragma unroll
    for (int j = 0; j < 8; ++j)
        lm = fmaxf(lm, fmaxf(fmaxf(f[j].x, f[j].y), fmaxf(f[j].z, f[j].w)));
    const float wm1  = warp_max(lm);
    const float thr1 = wm1 - 1.0f;     // wm1 <= rowmax -> superset threshold

    int cnt = 0;
    #pragma unroll
    for (int j = 0; j < 8; ++j)
        cnt += (f[j].x > thr1) + (f[j].y > thr1) + (f[j].z > thr1) + (f[j].w > thr1);
    int pre = cnt;
    #pragma unroll
    for (int o = 1; o < 32; o <<= 1) {
        int t = __shfl_up_sync(0xffffffffu, pre, o);
        if (lane >= o) pre += t;
    }
    int total = __shfl_sync(0xffffffffu, pre, 31);
    bool ovf = total > LISTCAP;
    if (!ovf) {
        int k = pre - cnt;
        #pragma unroll
        for (int j = 0; j < 8; ++j) {
            const int e = 4 * (j * 32 + lane);
            if (f[j].x > thr1) { Lv[k] = f[j].x; Li[k] = e;     ++k; }
            if (f[j].y > thr1) { Lv[k] = f[j].y; Li[k] = e + 1; ++k; }
            if (f[j].z > thr1) { Lv[k] = f[j].z; Li[k] = e + 2; ++k; }
            if (f[j].w > thr1) { Lv[k] = f[j].w; Li[k] = e + 3; ++k; }
        }
    }

    // ================= half 1: elements [1024, 2048) =================
    #pragma unroll
    for (int j = 0; j < 8; ++j) f[j] = src[(j + 8) * 32 + lane];
    float lm2 = -3.4e38f;
    #pragma unroll
    for (int j = 0; j < 8; ++j)
        lm2 = fmaxf(lm2, fmaxf(fmaxf(f[j].x, f[j].y), fmaxf(f[j].z, f[j].w)));
    const float wm2 = warp_max(lm2);
    const float mx  = fmaxf(wm1, wm2);
    const float thr = mx - 1.0f;       // exact active threshold (= tau_lo)

    int cnt2 = 0;
    #pragma unroll
    for (int j = 0; j < 8; ++j)
        cnt2 += (f[j].x > thr) + (f[j].y > thr) + (f[j].z > thr) + (f[j].w > thr);
    int pre2 = cnt2;
    #pragma unroll
    for (int o = 1; o < 32; o <<= 1) {
        int t = __shfl_up_sync(0xffffffffu, pre2, o);
        if (lane >= o) pre2 += t;
    }
    const int tot2 = __shfl_sync(0xffffffffu, pre2, 31);
    if (total + tot2 > LISTCAP) ovf = true;
    if (!ovf) {
        int k = total + (pre2 - cnt2);
        #pragma unroll
        for (int j = 0; j < 8; ++j) {
            const int e = 4 * ((j + 8) * 32 + lane);
            if (f[j].x > thr) { Lv[k] = f[j].x; Li[k] = e;     ++k; }
            if (f[j].y > thr) { Lv[k] = f[j].y; Li[k] = e + 1; ++k; }
            if (f[j].z > thr) { Lv[k] = f[j].z; Li[k] = e + 2; ++k; }
            if (f[j].w > thr) { Lv[k] = f[j].w; Li[k] = e + 3; ++k; }
        }
    }
    total += tot2;
    __syncwarp();   // publish list

    if (!ovf) {
        // ---- zero-fill output row early (streaming; p = 0 for inactives) ----
        const float4 z = make_float4(0.0f, 0.0f, 0.0f, 0.0f);
        #pragma unroll
        for (int j = 0; j < 16; ++j) __stcs(dst + j * 32 + lane, z);

        // ---- ballot round 1: lane i evaluates lo + step*i (lane 0 at lo) ----
        float lo = thr;                       // f(lo) >= 0 guaranteed
        float step = DM0 * (1.0f / 32.0f);
        {
            const float tm = lo + step * (float)lane;
            float s3 = 0.0f;
            for (int i = 0; i < total; ++i) {
                float c = fmaxf(Lv[i] - tm, 0.0f);
                s3 = fmaf(c * c, c, s3);
            }
            const unsigned b = __ballot_sync(0xffffffffu, s3 >= 1.0f);  // lane0 set
            const int m = 32 - __clz(b);      // highest satisfying lane + 1
            lo += step * (float)(m - 1);      // f(lo) >= 0
        }
        // ---- ballot round 2 (also accumulates s2 -> Newton 1 comes free) ----
        step *= (1.0f / 32.0f);
        float S2, S3;
        {
            const float tm = lo + step * (float)lane;
            float s2 = 0.0f, s3 = 0.0f;
            for (int i = 0; i < total; ++i) {
                float c = fmaxf(Lv[i] - tm, 0.0f);
                float c2 = c * c;
                s2 += c2;
                s3 = fmaf(c2, c, s3);
            }
            const unsigned b = __ballot_sync(0xffffffffu, s3 >= 1.0f);
            const int m = 32 - __clz(b);
            lo += step * (float)(m - 1);
            S2 = __shfl_sync(0xffffffffu, s2, m - 1);   // sums at the new lo
            S3 = __shfl_sync(0xffffffffu, s3, m - 1);
        }
        // ---- Newton 1 (free) + Newton 2 (one list pass) ----
        float tau = lo + __fdividef(S3 - 1.0f, 3.0f * S2);
        {
            float s2 = 0.0f, s3 = 0.0f;
            for (int i = 0; i < total; ++i) {
                float c = fmaxf(Lv[i] - tau, 0.0f);
                float c2 = c * c;
                s2 += c2;
                s3 = fmaf(c2, c, s3);
            }
            tau += __fdividef(s3 - 1.0f, 3.0f * s2);   // convex, from f>=0 side
        }
        // ---- normalization (redundant per lane, fixed order -> warp-uniform) ----
        float s2f = 0.0f;
        for (int i = 0; i < total; ++i) {
            float c = fmaxf(Lv[i] - tau, 0.0f);
            s2f = fmaf(c, c, s2f);
        }
        const float inv = __fdividef(1.0f, s2f);

        // ---- sparse scatter (ordered after zero-fill by __syncwarp) ----
        __syncwarp();
        float* __restrict__ orow = O + (size_t)w * D;
        for (int i = lane; i < total; i += 32) {
            const float c = fmaxf(Lv[i] - tau, 0.0f);
            if (c > 0.0f) orow[Li[i]] = c * c * inv;
        }
    } else {
        // ---- rare fallback: full-row solve + full-row write ----
        float tau_lo = thr, dm = DM0;
        for (int it = 0; it < NB_FB; ++it) {
            dm *= 0.5f;
            const float tm = tau_lo + dm;
            if (s3_g(src, lane, tm) >= 1.0f) tau_lo = tm;
        }
        float tau = tau_lo;
        for (int it = 0; it < NN_FB; ++it) {
            float rs2, rs3;
            s23_g(src, lane, tau, rs2, rs3);
            tau += __fdividef(rs3 - 1.0f, 3.0f * rs2);
        }
        float s2, dummy;
        s23_g(src, lane, tau, s2, dummy);
        const float inv = __fdividef(1.0f, s2);

        #pragma unroll 4
        for (int j = 0; j < 16; ++j) {
            float4 t = src[j * 32 + lane];
            float cx = fmaxf(t.x - tau, 0.0f), cy = fmaxf(t.y - tau, 0.0f);
            float cz = fmaxf(t.z - tau, 0.0f), cw = fmaxf(t.w - tau, 0.0f);
            float4 p;
            p.x = cx * cx * inv;
            p.y = cy * cy * inv;
            p.z = cz * cz * inv;
            p.w = cw * cw * inv;
            dst[j * 32 + lane] = p;
        }
    }
}

extern "C" void kernel_launch(void* const* d_in, const int* in_sizes, int n_in,
                              void* d_out, int out_size) {
    const float* X = (const float*)d_in[0];
    float* O = (float*)d_out;
    const int nrows = in_sizes[0] / D;                 // 65536
    const int grid = (nrows + WARPS - 1) / WARPS;
    normmax_trim_kernel<<<grid, THREADS>>>(X, O, nrows);
}